// round 7
// baseline (speedup 1.0000x reference)
#include <cuda_runtime.h>

typedef unsigned long long ull;

#define B_     128
#define QN     16
#define LN     2048
#define EMB_   128
#define KN     11
#define TPB    1024
#define DPP    1024            // docs per pass (1024 threads x 1 doc)
#define NC     8               // e-chunks per pass
#define EC     16              // e values per chunk
#define STG    (DPP*EC)        // words per stage buffer (16384 = 64KB)
#define NKH    6               // kernel centers per warp-half (half1 uses 5 + 1 dummy)

// ---------------- packed f32x2 helpers ----------------
__device__ __forceinline__ void fma2(ull& d, ull a, ull b) {
    asm("fma.rn.f32x2 %0, %1, %2, %0;" : "+l"(d) : "l"(a), "l"(b));
}
__device__ __forceinline__ ull add2(ull a, ull b) {
    ull r; asm("add.rn.f32x2 %0, %1, %2;" : "=l"(r) : "l"(a), "l"(b)); return r;
}
__device__ __forceinline__ ull mul2(ull a, ull b) {
    ull r; asm("mul.rn.f32x2 %0, %1, %2;" : "=l"(r) : "l"(a), "l"(b)); return r;
}
__device__ __forceinline__ ull pack2(float lo, float hi) {
    ull r; asm("mov.b64 %0, {%1, %2};" : "=l"(r) : "f"(lo), "f"(hi)); return r;
}
__device__ __forceinline__ float2 unpack2(ull v) {
    float2 r; asm("mov.b64 {%0, %1}, %2;" : "=f"(r.x), "=f"(r.y) : "l"(v)); return r;
}
__device__ __forceinline__ float ex2a(float x) {
    float r; asm("ex2.approx.f32 %0, %1;" : "=f"(r) : "f"(x)); return r;
}
__device__ __forceinline__ float lg2a(float x) {
    float r; asm("lg2.approx.f32 %0, %1;" : "=f"(r) : "f"(x)); return r;
}

// ---------------- cp.async (LDGSTS) helpers ----------------
__device__ __forceinline__ unsigned smaddr(const void* p) {
    unsigned r;
    asm("{ .reg .u64 t; cvta.to.shared.u64 t, %1; cvt.u32.u64 %0, t; }"
        : "=r"(r) : "l"(p));
    return r;
}
__device__ __forceinline__ void cp16(unsigned dst, const void* src) {
    asm volatile("cp.async.ca.shared.global [%0], [%1], 16;" :: "r"(dst), "l"(src));
}
__device__ __forceinline__ void cp_commit() { asm volatile("cp.async.commit_group;"); }
__device__ __forceinline__ void cp_wait1()  { asm volatile("cp.async.wait_group 1;"); }
__device__ __forceinline__ void cp_wait0()  { asm volatile("cp.async.wait_group 0;"); }

// word offset of (doc, quarter) in a stage buffer, XOR-swizzled for bank spread
__device__ __forceinline__ int sw_off(int doc, int q) {
    return doc * EC + ((q ^ ((doc >> 1) & 3)) << 2);
}

// RBF pooling over 2 sims (packed): NKH centers from this warp's mu base
#define RBF_ITER(it) do {                                                      \
    float s0 = sims[qrbf*DPP + lane + 64*(it)];                                \
    float s1 = sims[qrbf*DPP + lane + 64*(it) + 32];                           \
    ull dd = add2(pack2(s0, s1), MUB2);                                        \
    _Pragma("unroll")                                                          \
    for (int k = 0; k < NKH; ++k) {                                            \
        ull m = mul2(dd, dd);                                                  \
        ull t = mul2(m, C2);                                                   \
        float2 tf = unpack2(t);                                                \
        pk2[k] = add2(pk2[k], pack2(ex2a(tf.x), ex2a(tf.y)));                  \
        dd = add2(dd, MP2);                                                    \
    } } while (0)

extern "C" __global__ void __launch_bounds__(TPB, 1)
knrm_fused(const int* __restrict__ queries,
           const int* __restrict__ docs,
           const float* __restrict__ emb,
           const float* __restrict__ W,
           const float* __restrict__ bias,
           float* __restrict__ out)
{
    extern __shared__ __align__(16) float sm[];
    float* qsT   = sm;                          // [128][16]    8 KB (transposed [e][q])
    float* sims  = sm + EMB_*QN;                // [16][1024]  64 KB
    float* stage = sims + QN*DPP;               // 2 x [1024][16] 128 KB
    float* nsq   = stage + 2*STG;               // [16]
    float* parts = nsq + QN;                    // [32]

    const int b    = blockIdx.x;
    const int tid  = threadIdx.x;
    const int lane = tid & 31;
    const int w    = tid >> 5;                  // 32 warps
    const int qrbf = w & 15;                    // RBF query owned by this warp
    const int kh   = w >> 4;                    // k-half: 0 -> k0..5, 1 -> k6..10(+dummy)

    const unsigned stage_u32 = smaddr(stage);
    const int q4   = tid & 3;                   // staging quarter
    const int srow = tid >> 2;                  // staging doc row (0..255)

    // ---------- stage 1: gather + normalize queries into transposed smem ----------
    if (tid < QN) nsq[tid] = 0.0f;
    __syncthreads();
    if (tid < 512) {
        const int q1 = tid & 15;
        const int c1 = tid >> 4;                // 4-float chunk (0..31)
        const int qi = queries[b*QN + q1];
        float4 v = *(const float4*)(emb + (size_t)qi*EMB_ + c1*4);
        float ssq = v.x*v.x + v.y*v.y + v.z*v.z + v.w*v.w;
        ssq += __shfl_xor_sync(0xffffffffu, ssq, 16);
        if (lane < 16) atomicAdd(&nsq[q1], ssq);
    }
    __syncthreads();
    if (tid < 512) {
        const int q1 = tid & 15;
        const int c1 = tid >> 4;
        const int qi = queries[b*QN + q1];
        float4 v = *(const float4*)(emb + (size_t)qi*EMB_ + c1*4);
        float n  = nsq[q1];
        float rn = (n > 0.0f) ? rsqrtf(n) : 0.0f;   // padding row -> sim = 0
        qsT[(c1*4+0)*QN + q1] = v.x*rn;
        qsT[(c1*4+1)*QN + q1] = v.y*rn;
        qsT[(c1*4+2)*QN + q1] = v.z*rn;
        qsT[(c1*4+3)*QN + q1] = v.w*rn;
    }
    __syncthreads();

    ull pk2[NKH];
    #pragma unroll
    for (int k = 0; k < NKH; ++k) pk2[k] = 0ull;
    const float mub = 1.0f - 0.2f * (float)(kh * NKH);  // s - mu_base = s + mub
    const ull MUB2 = pack2(mub, mub);
    const ull MP2  = pack2(-0.2f, -0.2f);
    const ull C2   = pack2(-72.13475204f, -72.13475204f); // -50 * log2(e)

    #pragma unroll 1
    for (int pass = 0; pass < 2; ++pass) {
        // doc ids this thread stages (4 rows) and computes (doc = tid)
        int gid[4];
        #pragma unroll
        for (int r = 0; r < 4; ++r)
            gid[r] = docs[b*LN + pass*DPP + r*256 + srow];

        // issue chunk 0 into buffer 0
        #pragma unroll
        for (int r = 0; r < 4; ++r)
            cp16(stage_u32 + 4u*sw_off(r*256 + srow, q4),
                 emb + (size_t)gid[r]*EMB_ + q4*4);
        cp_commit();

        ull acc[8], ss2 = 0ull;
        #pragma unroll
        for (int i = 0; i < 8; ++i) acc[i] = 0ull;

        #pragma unroll 1
        for (int c = 0; c < NC; ++c) {
            if (c + 1 < NC) {
                const int buf = (c + 1) & 1;
                #pragma unroll
                for (int r = 0; r < 4; ++r)
                    cp16(stage_u32 + 4u*(buf*STG + sw_off(r*256 + srow, q4)),
                         emb + (size_t)gid[r]*EMB_ + (c + 1)*EC + q4*4);
                cp_commit();
                cp_wait1();
            } else {
                cp_wait0();
            }
            __syncthreads();

            // ---------- compute chunk c: 16 e's, 1 doc x 16 queries ----------
            const float* sbuf = stage + (c & 1)*STG;
            #pragma unroll
            for (int j = 0; j < 4; ++j) {
                ulonglong2 ap = *(const ulonglong2*)(sbuf + sw_off(tid, j));
                fma2(ss2, ap.x, ap.x);               // e-packed sumsq, no packing
                fma2(ss2, ap.y, ap.y);
                float2 a01 = unpack2(ap.x);
                float2 a23 = unpack2(ap.y);
                #pragma unroll
                for (int jj = 0; jj < 4; ++jj) {
                    float x = (jj==0)?a01.x:(jj==1)?a01.y:(jj==2)?a23.x:a23.y;
                    ull A = pack2(x, x);
                    const ulonglong2* qrow =
                        (const ulonglong2*)(qsT + (c*EC + j*4 + jj)*QN);
                    ulonglong2 qa = qrow[0];
                    ulonglong2 qb = qrow[1];
                    fma2(acc[0], A, qa.x); fma2(acc[1], A, qa.y);
                    fma2(acc[2], A, qb.x); fma2(acc[3], A, qb.y);
                    ulonglong2 qc = qrow[2];
                    ulonglong2 qd = qrow[3];
                    fma2(acc[4], A, qc.x); fma2(acc[5], A, qc.y);
                    fma2(acc[6], A, qd.x); fma2(acc[7], A, qd.y);
                }
            }

            // RBF of pass-0 sims interleaved into pass-1 dot (sims rewritten only after loop)
            if (pass == 1) {
                RBF_ITER(2*c);
                RBF_ITER(2*c + 1);
            }
            __syncthreads();
        }

        // ---------- norm + write sims (transpose to [q][doc]) ----------
        {
            float2 nn = unpack2(ss2);
            float n  = nn.x + nn.y;
            float rd = (n > 0.0f) ? rsqrtf(n) : 0.0f;  // padding doc -> sim 0
            #pragma unroll
            for (int qp = 0; qp < 8; ++qp) {
                float2 f = unpack2(acc[qp]);
                sims[(2*qp  )*DPP + tid] = f.x * rd;
                sims[(2*qp+1)*DPP + tid] = f.y * rd;
            }
        }
        __syncthreads();
    }

    // ---------- RBF over pass-1 sims (exposed tail) ----------
    #pragma unroll 2
    for (int it = 0; it < 16; ++it) RBF_ITER(it);

    // ---------- epilogue: per-warp reduce (its q, its k-range), log, W ----------
    {
        const int nk = kh ? (KN - NKH) : NKH;     // half1: 5 real centers (6th is dummy)
        float part = 0.0f;
        #pragma unroll
        for (int k = 0; k < NKH; ++k) {
            float2 h = unpack2(pk2[k]);
            float v = h.x + h.y;
            v += __shfl_xor_sync(0xffffffffu, v, 16);
            v += __shfl_xor_sync(0xffffffffu, v, 8);
            v += __shfl_xor_sync(0xffffffffu, v, 4);
            v += __shfl_xor_sync(0xffffffffu, v, 2);
            v += __shfl_xor_sync(0xffffffffu, v, 1);
            if (k < nk)
                part += __ldg(W + kh*NKH + k) * (lg2a(v) * 0.6931471805599453f);
        }
        if (lane == 0) parts[w] = part;
    }
    __syncthreads();
    if (tid == 0) {
        float s = __ldg(bias);
        #pragma unroll
        for (int i = 0; i < 32; ++i) s += parts[i];
        out[b] = 1.0f / (1.0f + __expf(-s));
    }
}

extern "C" void kernel_launch(void* const* d_in, const int* in_sizes, int n_in,
                              void* d_out, int out_size)
{
    const int*   queries = (const int*)d_in[0];
    const int*   docs    = (const int*)d_in[1];
    const float* emb     = (const float*)d_in[2];
    const float* W       = (const float*)d_in[3];
    const float* bias    = (const float*)d_in[4];
    float*       out     = (float*)d_out;

    const int smem = (EMB_*QN + QN*DPP + 2*STG + QN + 32) * (int)sizeof(float); // ~200 KB
    cudaFuncSetAttribute(knrm_fused, cudaFuncAttributeMaxDynamicSharedMemorySize, smem);

    knrm_fused<<<B_, TPB, smem>>>(queries, docs, emb, W, bias, out);
}

// round 8
// speedup vs baseline: 2.1702x; 2.1702x over previous
#include <cuda_runtime.h>

typedef unsigned long long ull;

#define B_     128
#define QN     16
#define LN     2048
#define EMB_   128
#define KN     11
#define TPB    512
#define NW     16              // warps per CTA
#define WD     64              // docs per warp per pass
#define DPP    1024            // docs per pass
#define EC     16              // e values per chunk
#define NC     8               // chunks per pass (EMB_/EC)
#define WBUF   (WD*EC)         // words per warp stage buffer (1024 = 4KB)

// ---------------- packed f32x2 helpers ----------------
__device__ __forceinline__ void fma2(ull& d, ull a, ull b) {
    asm("fma.rn.f32x2 %0, %1, %2, %0;" : "+l"(d) : "l"(a), "l"(b));
}
__device__ __forceinline__ ull add2(ull a, ull b) {
    ull r; asm("add.rn.f32x2 %0, %1, %2;" : "=l"(r) : "l"(a), "l"(b)); return r;
}
__device__ __forceinline__ ull mul2(ull a, ull b) {
    ull r; asm("mul.rn.f32x2 %0, %1, %2;" : "=l"(r) : "l"(a), "l"(b)); return r;
}
__device__ __forceinline__ ull pack2(float lo, float hi) {
    ull r; asm("mov.b64 %0, {%1, %2};" : "=l"(r) : "f"(lo), "f"(hi)); return r;
}
__device__ __forceinline__ float2 unpack2(ull v) {
    float2 r; asm("mov.b64 {%0, %1}, %2;" : "=f"(r.x), "=f"(r.y) : "l"(v)); return r;
}
__device__ __forceinline__ float ex2a(float x) {
    float r; asm("ex2.approx.f32 %0, %1;" : "=f"(r) : "f"(x)); return r;
}
__device__ __forceinline__ float lg2a(float x) {
    float r; asm("lg2.approx.f32 %0, %1;" : "=f"(r) : "f"(x)); return r;
}

// ---------------- cp.async helpers ----------------
__device__ __forceinline__ unsigned smaddr(const void* p) {
    unsigned r;
    asm("{ .reg .u64 t; cvta.to.shared.u64 t, %1; cvt.u32.u64 %0, t; }"
        : "=r"(r) : "l"(p));
    return r;
}
__device__ __forceinline__ void cp16(unsigned dst, const void* src) {
    asm volatile("cp.async.ca.shared.global [%0], [%1], 16;" :: "r"(dst), "l"(src));
}
__device__ __forceinline__ void cp_commit() { asm volatile("cp.async.commit_group;"); }
__device__ __forceinline__ void cp_wait1()  { asm volatile("cp.async.wait_group 1;"); }
__device__ __forceinline__ void cp_wait0()  { asm volatile("cp.async.wait_group 0;"); }

// word offset of (doc, quarter) in a warp stage buffer, XOR-swizzled
__device__ __forceinline__ int sw_off(int doc, int q) {
    return doc * EC + ((q ^ ((doc >> 1) & 3)) << 2);
}

// RBF pooling over 2 sims (packed): 11 centers via incremental mu += 0.2
#define RBF_ITER(it) do {                                                      \
    float s0 = sims[w*DPP + lane + 64*(it)];                                   \
    float s1 = sims[w*DPP + lane + 64*(it) + 32];                              \
    ull dd = add2(pack2(s0, s1), ONE2);                                        \
    _Pragma("unroll")                                                          \
    for (int k = 0; k < KN; ++k) {                                             \
        ull m = mul2(dd, dd);                                                  \
        ull t = mul2(m, C2);                                                   \
        float2 tf = unpack2(t);                                                \
        pk2[k] = add2(pk2[k], pack2(ex2a(tf.x), ex2a(tf.y)));                  \
        dd = add2(dd, MP2);                                                    \
    } } while (0)

extern "C" __global__ void __launch_bounds__(TPB, 1)
knrm_fused(const int* __restrict__ queries,
           const int* __restrict__ docs,
           const float* __restrict__ emb,
           const float* __restrict__ W,
           const float* __restrict__ bias,
           float* __restrict__ out)
{
    extern __shared__ __align__(16) float sm[];
    float* qsT   = sm;                          // [128][16]       8 KB (transposed [e][q])
    float* sims  = sm + EMB_*QN;                // [16][1024]     64 KB
    float* stage = sims + QN*DPP;               // 16 warps x 2 x 4KB = 128 KB
    float* nsq   = stage + NW*2*WBUF;           // [16]
    float* parts = nsq + QN;                    // [16]

    const int b    = blockIdx.x;
    const int tid  = threadIdx.x;
    const int lane = tid & 31;
    const int w    = tid >> 5;                  // warp id; owns docs [w*64,w*64+64) and query w for RBF

    const unsigned wstage_u32 = smaddr(stage) + 4u * (unsigned)(w * 2 * WBUF);
    float* wstage = stage + w * 2 * WBUF;
    const int q4 = lane & 3;                    // staging quarter (16B)

    // ---------- stage 1: gather + normalize queries into transposed smem ----------
    if (tid < QN) nsq[tid] = 0.0f;
    __syncthreads();
    {
        const int q1 = tid & 15;                // query
        const int c1 = tid >> 4;                // 4-float chunk (0..31)
        const int qi = queries[b*QN + q1];
        float4 v = *(const float4*)(emb + (size_t)qi*EMB_ + c1*4);
        float ssq = v.x*v.x + v.y*v.y + v.z*v.z + v.w*v.w;
        ssq += __shfl_xor_sync(0xffffffffu, ssq, 16);
        if (lane < 16) atomicAdd(&nsq[q1], ssq);
        __syncthreads();
        float n  = nsq[q1];
        float rn = (n > 0.0f) ? rsqrtf(n) : 0.0f;   // padding row -> sim = 0
        qsT[(c1*4+0)*QN + q1] = v.x*rn;
        qsT[(c1*4+1)*QN + q1] = v.y*rn;
        qsT[(c1*4+2)*QN + q1] = v.z*rn;
        qsT[(c1*4+3)*QN + q1] = v.w*rn;
    }
    __syncthreads();

    ull pk2[KN];
    #pragma unroll
    for (int k = 0; k < KN; ++k) pk2[k] = 0ull;
    const ull ONE2 = pack2(1.0f, 1.0f);
    const ull MP2  = pack2(-0.2f, -0.2f);
    const ull C2   = pack2(-72.13475204f, -72.13475204f); // -50 * log2(e)

    #pragma unroll 1
    for (int pass = 0; pass < 2; ++pass) {
        // doc ids this lane stages: local docs (lane>>2) + 8i, quarter q4
        int gid_s[8];
        {
            const int base = b*LN + pass*DPP + w*WD;
            #pragma unroll
            for (int i = 0; i < 8; ++i)
                gid_s[i] = docs[base + (lane >> 2) + 8*i];
        }

        // prologue: issue chunk 0 into warp buffer 0
        #pragma unroll
        for (int i = 0; i < 8; ++i)
            cp16(wstage_u32 + 4u*sw_off((lane >> 2) + 8*i, q4),
                 emb + (size_t)gid_s[i]*EMB_ + q4*4);
        cp_commit();

        ull acc0[8], acc1[8], ssA = 0ull, ssB = 0ull;
        #pragma unroll
        for (int i = 0; i < 8; ++i) { acc0[i] = 0ull; acc1[i] = 0ull; }

        #pragma unroll 1
        for (int c = 0; c < NC; ++c) {
            __syncwarp();                        // all lanes done reading buf (c-1)&1
            if (c + 1 < NC) {
                const int buf = (c + 1) & 1;
                #pragma unroll
                for (int i = 0; i < 8; ++i)
                    cp16(wstage_u32 + 4u*(buf*WBUF + sw_off((lane >> 2) + 8*i, q4)),
                         emb + (size_t)gid_s[i]*EMB_ + (c + 1)*EC + q4*4);
                cp_commit();
                cp_wait1();
            } else {
                cp_wait0();
            }
            __syncwarp();                        // chunk c data visible warp-wide

            // ---------- compute chunk c: 16 e's, 2 docs x 16 queries ----------
            const float* sbuf = wstage + (c & 1)*WBUF;
            #pragma unroll
            for (int j = 0; j < 4; ++j) {
                ulonglong2 a0 = *(const ulonglong2*)(sbuf + sw_off(lane,      j));
                ulonglong2 a1 = *(const ulonglong2*)(sbuf + sw_off(lane + 32, j));
                fma2(ssA, a0.x, a0.x); fma2(ssA, a0.y, a0.y);
                fma2(ssB, a1.x, a1.x); fma2(ssB, a1.y, a1.y);
                float2 e01 = unpack2(a0.x);
                float2 e23 = unpack2(a0.y);
                float2 f01 = unpack2(a1.x);
                float2 f23 = unpack2(a1.y);
                #pragma unroll
                for (int jj = 0; jj < 4; ++jj) {
                    float x0 = (jj==0)?e01.x:(jj==1)?e01.y:(jj==2)?e23.x:e23.y;
                    float x1 = (jj==0)?f01.x:(jj==1)?f01.y:(jj==2)?f23.x:f23.y;
                    ull A0 = pack2(x0, x0);
                    ull A1 = pack2(x1, x1);
                    const ulonglong2* qrow =
                        (const ulonglong2*)(qsT + (c*EC + j*4 + jj)*QN);
                    ulonglong2 qa = qrow[0];
                    ulonglong2 qb = qrow[1];
                    fma2(acc0[0], A0, qa.x); fma2(acc0[1], A0, qa.y);
                    fma2(acc0[2], A0, qb.x); fma2(acc0[3], A0, qb.y);
                    fma2(acc1[0], A1, qa.x); fma2(acc1[1], A1, qa.y);
                    fma2(acc1[2], A1, qb.x); fma2(acc1[3], A1, qb.y);
                    ulonglong2 qc = qrow[2];
                    ulonglong2 qd = qrow[3];
                    fma2(acc0[4], A0, qc.x); fma2(acc0[5], A0, qc.y);
                    fma2(acc0[6], A0, qd.x); fma2(acc0[7], A0, qd.y);
                    fma2(acc1[4], A1, qc.x); fma2(acc1[5], A1, qc.y);
                    fma2(acc1[6], A1, qd.x); fma2(acc1[7], A1, qd.y);
                }
            }

            // RBF of pass-0 sims interleaved into pass-1 dot (warp-local, no barrier)
            if (pass == 1) {
                RBF_ITER(2*c);
                RBF_ITER(2*c + 1);
            }
        }

        // ---------- norms + sims transpose (the only CTA-wide sync points) ----------
        {
            float2 na = unpack2(ssA);
            float2 nb = unpack2(ssB);
            float n0 = na.x + na.y;
            float n1 = nb.x + nb.y;
            float rd0 = (n0 > 0.0f) ? rsqrtf(n0) : 0.0f;  // padding doc -> sim 0
            float rd1 = (n1 > 0.0f) ? rsqrtf(n1) : 0.0f;

            if (pass == 1) __syncthreads();      // all warps done reading pass-0 sims
            const int col = w*WD + lane;
            #pragma unroll
            for (int qp = 0; qp < 8; ++qp) {
                float2 f0 = unpack2(acc0[qp]);
                float2 f1 = unpack2(acc1[qp]);
                sims[(2*qp  )*DPP + col]      = f0.x * rd0;
                sims[(2*qp+1)*DPP + col]      = f0.y * rd0;
                sims[(2*qp  )*DPP + col + 32] = f1.x * rd1;
                sims[(2*qp+1)*DPP + col + 32] = f1.y * rd1;
            }
        }
        __syncthreads();                         // sims visible to all warps
    }

    // ---------- RBF over pass-1 sims (exposed tail) ----------
    #pragma unroll 2
    for (int it = 0; it < 16; ++it) RBF_ITER(it);

    // ---------- epilogue: per-warp (per-query) reduce, log, W, sigmoid ----------
    float part = 0.0f;
    #pragma unroll
    for (int k = 0; k < KN; ++k) {
        float2 h = unpack2(pk2[k]);
        float v = h.x + h.y;
        v += __shfl_xor_sync(0xffffffffu, v, 16);
        v += __shfl_xor_sync(0xffffffffu, v, 8);
        v += __shfl_xor_sync(0xffffffffu, v, 4);
        v += __shfl_xor_sync(0xffffffffu, v, 2);
        v += __shfl_xor_sync(0xffffffffu, v, 1);
        part += __ldg(W + k) * (lg2a(v) * 0.6931471805599453f);
    }
    if (lane == 0) parts[w] = part;
    __syncthreads();
    if (tid == 0) {
        float s = __ldg(bias);
        #pragma unroll
        for (int i = 0; i < NW; ++i) s += parts[i];
        out[b] = 1.0f / (1.0f + __expf(-s));
    }
}

extern "C" void kernel_launch(void* const* d_in, const int* in_sizes, int n_in,
                              void* d_out, int out_size)
{
    const int*   queries = (const int*)d_in[0];
    const int*   docs    = (const int*)d_in[1];
    const float* emb     = (const float*)d_in[2];
    const float* W       = (const float*)d_in[3];
    const float* bias    = (const float*)d_in[4];
    float*       out     = (float*)d_out;

    const int smem = (EMB_*QN + QN*DPP + NW*2*WBUF + 2*QN) * (int)sizeof(float); // ~200 KB
    cudaFuncSetAttribute(knrm_fused, cudaFuncAttributeMaxDynamicSharedMemorySize, smem);

    knrm_fused<<<B_, TPB, smem>>>(queries, docs, emb, W, bias, out);
}

// round 10
// speedup vs baseline: 2.6555x; 1.2236x over previous
#include <cuda_runtime.h>

typedef unsigned long long ull;

#define B_     128
#define QN     16
#define LN     2048
#define EMB_   128
#define KN     11
#define TPB    512
#define NW     16              // warps per CTA
#define WD     64              // docs per warp per pass
#define DPP    1024            // docs per pass
#define EC     16              // e values per chunk
#define NC     8               // chunks per pass (EMB_/EC)
#define WBUF   (WD*EC)         // words per warp stage buffer (1024 = 4KB)

// ---------------- packed f32x2 helpers ----------------
__device__ __forceinline__ void fma2(ull& d, ull a, ull b) {
    asm("fma.rn.f32x2 %0, %1, %2, %0;" : "+l"(d) : "l"(a), "l"(b));
}
__device__ __forceinline__ ull add2(ull a, ull b) {
    ull r; asm("add.rn.f32x2 %0, %1, %2;" : "=l"(r) : "l"(a), "l"(b)); return r;
}
__device__ __forceinline__ ull mul2(ull a, ull b) {
    ull r; asm("mul.rn.f32x2 %0, %1, %2;" : "=l"(r) : "l"(a), "l"(b)); return r;
}
__device__ __forceinline__ ull pack2(float lo, float hi) {
    ull r; asm("mov.b64 %0, {%1, %2};" : "=l"(r) : "f"(lo), "f"(hi)); return r;
}
__device__ __forceinline__ float2 unpack2(ull v) {
    float2 r; asm("mov.b64 {%0, %1}, %2;" : "=f"(r.x), "=f"(r.y) : "l"(v)); return r;
}
__device__ __forceinline__ float ex2a(float x) {
    float r; asm("ex2.approx.f32 %0, %1;" : "=f"(r) : "f"(x)); return r;
}
__device__ __forceinline__ float lg2a(float x) {
    float r; asm("lg2.approx.f32 %0, %1;" : "=f"(r) : "f"(x)); return r;
}

// ---------------- cp.async helpers ----------------
__device__ __forceinline__ unsigned smaddr(const void* p) {
    unsigned r;
    asm("{ .reg .u64 t; cvta.to.shared.u64 t, %1; cvt.u32.u64 %0, t; }"
        : "=r"(r) : "l"(p));
    return r;
}
__device__ __forceinline__ void cp16(unsigned dst, const void* src) {
    asm volatile("cp.async.cg.shared.global [%0], [%1], 16;" :: "r"(dst), "l"(src));
}
__device__ __forceinline__ void cp_commit() { asm volatile("cp.async.commit_group;"); }
__device__ __forceinline__ void cp_wait1()  { asm volatile("cp.async.wait_group 1;"); }
__device__ __forceinline__ void cp_wait0()  { asm volatile("cp.async.wait_group 0;"); }

// word offset of (doc, quarter) in a warp stage buffer, XOR-swizzled
__device__ __forceinline__ int sw_off(int doc, int q) {
    return doc * EC + ((q ^ ((doc >> 1) & 3)) << 2);
}

// stage one 16-e chunk of this warp's 64 docs into buffer `buf`
#define STAGE_CHUNK(buf, ch) do {                                              \
    _Pragma("unroll")                                                          \
    for (int i_ = 0; i_ < 8; ++i_)                                             \
        cp16(wstage_u32 + 4u*((buf)*WBUF + sw_off((lane >> 2) + 8*i_, q4)),    \
             emb + (size_t)gid_s[i_]*EMB_ + (ch)*EC + q4*4);                   \
    cp_commit(); } while (0)

// RBF pooling over 2 adjacent sims (packed): 11 centers via incremental mu += 0.2
#define RBF_ITER(it) do {                                                      \
    float2 s01 = *(const float2*)(sims + w*DPP + 2*lane + 64*(it));            \
    ull dd = add2(pack2(s01.x, s01.y), ONE2);                                  \
    _Pragma("unroll")                                                          \
    for (int k = 0; k < KN; ++k) {                                             \
        ull m = mul2(dd, dd);                                                  \
        ull t = mul2(m, C2);                                                   \
        float2 tf = unpack2(t);                                                \
        pk2[k] = add2(pk2[k], pack2(ex2a(tf.x), ex2a(tf.y)));                  \
        dd = add2(dd, MP2);                                                    \
    } } while (0)

extern "C" __global__ void __launch_bounds__(TPB, 1)
knrm_fused(const int* __restrict__ queries,
           const int* __restrict__ docs,
           const float* __restrict__ emb,
           const float* __restrict__ W,
           const float* __restrict__ bias,
           float* __restrict__ out)
{
    extern __shared__ __align__(16) float sm[];
    float* qsT   = sm;                          // [128][16]       8 KB (transposed [e][q])
    float* sims  = sm + EMB_*QN;                // [16][1024]     64 KB
    float* stage = sims + QN*DPP;               // 16 warps x 2 x 4KB = 128 KB
    float* nsq   = stage + NW*2*WBUF;           // [16]
    float* parts = nsq + QN;                    // [16]

    const int b    = blockIdx.x;
    const int tid  = threadIdx.x;
    const int lane = tid & 31;
    const int w    = tid >> 5;                  // warp id; owns docs [w*64,w*64+64) and query w for RBF

    const unsigned wstage_u32 = smaddr(stage) + 4u * (unsigned)(w * 2 * WBUF);
    float* wstage = stage + w * 2 * WBUF;
    const int q4 = lane & 3;                    // staging quarter (16B)

    // ---------- startup: pass-0 gids + chunk-0 staging in flight FIRST ----------
    int gid_s[8];
    {
        const int base = b*LN + w*WD;
        #pragma unroll
        for (int i = 0; i < 8; ++i)
            gid_s[i] = docs[base + (lane >> 2) + 8*i];
    }
    STAGE_CHUNK(0, 0);                          // overlaps the whole query stage below

    // ---------- stage 1: gather + normalize queries into transposed smem ----------
    if (tid < QN) nsq[tid] = 0.0f;
    __syncthreads();
    {
        const int q1 = tid & 15;                // query
        const int c1 = tid >> 4;                // 4-float chunk (0..31)
        const int qi = queries[b*QN + q1];
        float4 v = *(const float4*)(emb + (size_t)qi*EMB_ + c1*4);
        float ssq = v.x*v.x + v.y*v.y + v.z*v.z + v.w*v.w;
        ssq += __shfl_xor_sync(0xffffffffu, ssq, 16);
        if (lane < 16) atomicAdd(&nsq[q1], ssq);
        __syncthreads();
        float n  = nsq[q1];
        float rn = (n > 0.0f) ? rsqrtf(n) : 0.0f;   // padding row -> sim = 0
        qsT[(c1*4+0)*QN + q1] = v.x*rn;
        qsT[(c1*4+1)*QN + q1] = v.y*rn;
        qsT[(c1*4+2)*QN + q1] = v.z*rn;
        qsT[(c1*4+3)*QN + q1] = v.w*rn;
    }
    __syncthreads();

    ull pk2[KN];
    #pragma unroll
    for (int k = 0; k < KN; ++k) pk2[k] = 0ull;
    const ull ONE2 = pack2(1.0f, 1.0f);
    const ull MP2  = pack2(-0.2f, -0.2f);
    const ull C2   = pack2(-72.13475204f, -72.13475204f); // -50 * log2(e)

    #pragma unroll 1
    for (int pass = 0; pass < 2; ++pass) {
        ull acc0[8], acc1[8], ssA = 0ull, ssB = 0ull;
        #pragma unroll
        for (int i = 0; i < 8; ++i) { acc0[i] = 0ull; acc1[i] = 0ull; }

        #pragma unroll 1
        for (int c = 0; c < NC; ++c) {
            __syncwarp();                        // all lanes done reading buf (c+1)&1 (chunk c-1)
            if (c + 1 < NC) {
                STAGE_CHUNK((c + 1) & 1, c + 1);
                cp_wait1();
            } else {
                cp_wait0();
            }
            __syncwarp();                        // chunk c data visible warp-wide

            // ---------- compute chunk c: 16 e's, 2 docs x 16 queries ----------
            const float* sbuf = wstage + (c & 1)*WBUF;
            #pragma unroll
            for (int j = 0; j < 4; ++j) {
                ulonglong2 a0 = *(const ulonglong2*)(sbuf + sw_off(lane,      j));
                ulonglong2 a1 = *(const ulonglong2*)(sbuf + sw_off(lane + 32, j));
                fma2(ssA, a0.x, a0.x); fma2(ssA, a0.y, a0.y);
                fma2(ssB, a1.x, a1.x); fma2(ssB, a1.y, a1.y);
                float2 e01 = unpack2(a0.x);
                float2 e23 = unpack2(a0.y);
                float2 f01 = unpack2(a1.x);
                float2 f23 = unpack2(a1.y);
                #pragma unroll
                for (int jj = 0; jj < 4; ++jj) {
                    float x0 = (jj==0)?e01.x:(jj==1)?e01.y:(jj==2)?e23.x:e23.y;
                    float x1 = (jj==0)?f01.x:(jj==1)?f01.y:(jj==2)?f23.x:f23.y;
                    ull A0 = pack2(x0, x0);
                    ull A1 = pack2(x1, x1);
                    const ulonglong2* qrow =
                        (const ulonglong2*)(qsT + (c*EC + j*4 + jj)*QN);
                    ulonglong2 qa = qrow[0];
                    ulonglong2 qb = qrow[1];
                    fma2(acc0[0], A0, qa.x); fma2(acc0[1], A0, qa.y);
                    fma2(acc0[2], A0, qb.x); fma2(acc0[3], A0, qb.y);
                    fma2(acc1[0], A1, qa.x); fma2(acc1[1], A1, qa.y);
                    fma2(acc1[2], A1, qb.x); fma2(acc1[3], A1, qb.y);
                    ulonglong2 qc = qrow[2];
                    ulonglong2 qd = qrow[3];
                    fma2(acc0[4], A0, qc.x); fma2(acc0[5], A0, qc.y);
                    fma2(acc0[6], A0, qd.x); fma2(acc0[7], A0, qd.y);
                    fma2(acc1[4], A1, qc.x); fma2(acc1[5], A1, qc.y);
                    fma2(acc1[6], A1, qd.x); fma2(acc1[7], A1, qd.y);
                }
            }

            // RBF of pass-0 sims interleaved into pass-1 dot (warp-local, no barrier)
            if (pass == 1) {
                RBF_ITER(2*c);
                RBF_ITER(2*c + 1);
            }
        }

        // ---------- inter-pass overlap: pass-1 gids + its chunk-0 staging NOW ----------
        // (hides staging latency under norms + sims writes + both CTA barriers;
        //  buffer 0 was last read at chunk 6, all lanes past that point)
        if (pass == 0) {
            const int base = b*LN + DPP + w*WD;
            #pragma unroll
            for (int i = 0; i < 8; ++i)
                gid_s[i] = docs[base + (lane >> 2) + 8*i];
            STAGE_CHUNK(0, 0);
        }

        // ---------- norms + sims transpose (the only CTA-wide sync points) ----------
        {
            float2 na = unpack2(ssA);
            float2 nb = unpack2(ssB);
            float n0 = na.x + na.y;
            float n1 = nb.x + nb.y;
            float rd0 = (n0 > 0.0f) ? rsqrtf(n0) : 0.0f;  // padding doc -> sim 0
            float rd1 = (n1 > 0.0f) ? rsqrtf(n1) : 0.0f;

            if (pass == 1) __syncthreads();      // all warps done reading pass-0 sims
            const int col = w*WD + lane;
            #pragma unroll
            for (int qp = 0; qp < 8; ++qp) {
                float2 f0 = unpack2(acc0[qp]);
                float2 f1 = unpack2(acc1[qp]);
                sims[(2*qp  )*DPP + col]      = f0.x * rd0;
                sims[(2*qp+1)*DPP + col]      = f0.y * rd0;
                sims[(2*qp  )*DPP + col + 32] = f1.x * rd1;
                sims[(2*qp+1)*DPP + col + 32] = f1.y * rd1;
            }
        }
        __syncthreads();                         // sims visible to all warps
    }

    // ---------- RBF over pass-1 sims (exposed tail) ----------
    #pragma unroll 2
    for (int it = 0; it < 16; ++it) RBF_ITER(it);

    // ---------- epilogue: per-warp (per-query) reduce, log, W, sigmoid ----------
    float part = 0.0f;
    #pragma unroll
    for (int k = 0; k < KN; ++k) {
        float2 h = unpack2(pk2[k]);
        float v = h.x + h.y;
        v += __shfl_xor_sync(0xffffffffu, v, 16);
        v += __shfl_xor_sync(0xffffffffu, v, 8);
        v += __shfl_xor_sync(0xffffffffu, v, 4);
        v += __shfl_xor_sync(0xffffffffu, v, 2);
        v += __shfl_xor_sync(0xffffffffu, v, 1);
        part += __ldg(W + k) * (lg2a(v) * 0.6931471805599453f);
    }
    if (lane == 0) parts[w] = part;
    __syncthreads();
    if (tid == 0) {
        float s = __ldg(bias);
        #pragma unroll
        for (int i = 0; i < NW; ++i) s += parts[i];
        out[b] = 1.0f / (1.0f + __expf(-s));
    }
}

extern "C" void kernel_launch(void* const* d_in, const int* in_sizes, int n_in,
                              void* d_out, int out_size)
{
    const int*   queries = (const int*)d_in[0];
    const int*   docs    = (const int*)d_in[1];
    const float* emb     = (const float*)d_in[2];
    const float* W       = (const float*)d_in[3];
    const float* bias    = (const float*)d_in[4];
    float*       out     = (float*)d_out;

    const int smem = (EMB_*QN + QN*DPP + NW*2*WBUF + 2*QN) * (int)sizeof(float); // ~200 KB
    cudaFuncSetAttribute(knrm_fused, cudaFuncAttributeMaxDynamicSharedMemorySize, smem);

    knrm_fused<<<B_, TPB, smem>>>(queries, docs, emb, W, bias, out);
}